// round 2
// baseline (speedup 1.0000x reference)
#include <cuda_runtime.h>
#include <math.h>
#include <stdint.h>

// Problem dims (fixed by the dataset)
#define BATCH 512
#define DIM   256
#define NKEYS 262144
#define TOPK  256
#define CAND_CAP 4096
#define NBINS 8192          // top 13 bits of monotone float key

// ---------------- device scratch (no allocations allowed) ----------------
__device__ float               g_q[BATCH * DIM];
__device__ float               g_scores[(size_t)BATCH * NKEYS];     // 512 MB
__device__ int                 g_thr[BATCH];
__device__ int                 g_cand_count[BATCH];
__device__ unsigned long long  g_cand[(size_t)BATCH * CAND_CAP];    // packed (score,idx) keys
__device__ float               g_topk_score[BATCH * TOPK];
__device__ int                 g_topk_idx[BATCH * TOPK];
__device__ float               g_loss;

// Monotone float<->uint mapping: larger float => larger uint
__device__ __forceinline__ unsigned monof(float f) {
    unsigned u = __float_as_uint(f);
    return (u & 0x80000000u) ? ~u : (u | 0x80000000u);
}
__device__ __forceinline__ float unmonof(unsigned m) {
    return (m & 0x80000000u) ? __uint_as_float(m ^ 0x80000000u)
                             : __uint_as_float(~m);
}

// Packed f32x2 helpers (sm_100+): each 64-bit reg holds two IEEE fp32 lanes.
__device__ __forceinline__ void ffma2(unsigned long long& d,
                                      unsigned long long a,
                                      unsigned long long b) {
    asm("fma.rn.f32x2 %0, %1, %2, %0;" : "+l"(d) : "l"(a), "l"(b));
}
__device__ __forceinline__ unsigned long long dup2(float x) {
    unsigned long long r;
    asm("mov.b64 %0, {%1, %1};" : "=l"(r) : "f"(x));
    return r;
}

// ---------------- kernel 0: per-launch init ----------------
__global__ void init_kernel() {
    int i = threadIdx.x;
    if (i < BATCH) g_cand_count[i] = 0;
    if (i == 0) g_loss = 0.0f;
}

// ---------------- kernel 1: q = normalize(x @ W^T + b) ----------------
__global__ void q_kernel(const float* __restrict__ x,
                         const float* __restrict__ W,
                         const float* __restrict__ bias) {
    __shared__ float xs[DIM];
    __shared__ float red[DIM];
    int row = blockIdx.x;
    int j   = threadIdx.x;
    xs[j] = x[row * DIM + j];
    __syncthreads();
    const float* wr = W + j * DIM;
    float acc = 0.0f;
#pragma unroll 8
    for (int d = 0; d < DIM; ++d) acc = fmaf(xs[d], wr[d], acc);
    acc += bias[j];
    red[j] = acc * acc;
    __syncthreads();
    for (int s = DIM / 2; s > 0; s >>= 1) {
        if (j < s) red[j] += red[j + s];
        __syncthreads();
    }
    // same scale factor for the whole row -> score ordering is exact
    float inv = rsqrtf(red[0]);
    g_q[row * DIM + j] = acc * inv;
}

// ---------------- kernel 2: scores = q @ keys^T (fp32 SGEMM, f32x2 core) ----
// Tile 128(batch) x 128(keys) x 16(K). 256 threads, 8x8 per thread.
// Accumulators are packed f32x2 (pairs along the key axis).
#define BM 128
#define BN 128
#define BK 16
__global__ void __launch_bounds__(256)
score_gemm(const float* __restrict__ keys) {
    __shared__ float As[BK][BM];
    __shared__ float Bs[BK][BN];
    int tid = threadIdx.x;
    int tx  = tid & 15;        // key sub-tile
    int ty  = tid >> 4;        // batch sub-tile
    int nBase = blockIdx.x * BN;
    int mBase = blockIdx.y * BM;

    unsigned long long acc[8][4];   // [i][j-pair], each holds 2 fp32 columns
#pragma unroll
    for (int i = 0; i < 8; ++i)
#pragma unroll
        for (int j = 0; j < 4; ++j) acc[i][j] = 0ULL;

    for (int k0 = 0; k0 < DIM; k0 += BK) {
        // load A tile (q) and B tile (keys), transposed into [k][mn]
#pragma unroll
        for (int r = 0; r < 2; ++r) {
            int f4id = tid + r * 256;          // 0..511
            int row  = f4id >> 2;              // 0..127
            int kk4  = (f4id & 3) * 4;         // 0,4,8,12
            float4 va = *(const float4*)&g_q[(size_t)(mBase + row) * DIM + k0 + kk4];
            As[kk4 + 0][row] = va.x; As[kk4 + 1][row] = va.y;
            As[kk4 + 2][row] = va.z; As[kk4 + 3][row] = va.w;
            float4 vb = *(const float4*)&keys[(size_t)(nBase + row) * DIM + k0 + kk4];
            Bs[kk4 + 0][row] = vb.x; Bs[kk4 + 1][row] = vb.y;
            Bs[kk4 + 2][row] = vb.z; Bs[kk4 + 3][row] = vb.w;
        }
        __syncthreads();
#pragma unroll
        for (int kk = 0; kk < BK; ++kk) {
            // a: 8 scalars (rows), b: 8 columns as 4 packed pairs (LDS.128 x2)
            float4 a0 = *(const float4*)&As[kk][ty * 8];
            float4 a1 = *(const float4*)&As[kk][ty * 8 + 4];
            ulonglong2 bp0 = *(const ulonglong2*)&Bs[kk][tx * 8];      // cols 0-3
            ulonglong2 bp1 = *(const ulonglong2*)&Bs[kk][tx * 8 + 4];  // cols 4-7
            unsigned long long b[4] = { bp0.x, bp0.y, bp1.x, bp1.y };
            float a[8] = { a0.x, a0.y, a0.z, a0.w, a1.x, a1.y, a1.z, a1.w };
#pragma unroll
            for (int i = 0; i < 8; ++i) {
                unsigned long long ai = dup2(a[i]);
#pragma unroll
                for (int j = 0; j < 4; ++j) ffma2(acc[i][j], ai, b[j]);
            }
        }
        __syncthreads();
    }
#pragma unroll
    for (int i = 0; i < 8; ++i) {
        float* dst = &g_scores[(size_t)(mBase + ty * 8 + i) * NKEYS + nBase + tx * 8];
        ulonglong2 s0 = make_ulonglong2(acc[i][0], acc[i][1]);
        ulonglong2 s1 = make_ulonglong2(acc[i][2], acc[i][3]);
        *(ulonglong2*)(dst)     = s0;   // 16B store, cols 0-3
        *(ulonglong2*)(dst + 4) = s1;   // 16B store, cols 4-7
    }
}

// ---------------- kernel 3: per-row 13-bit histogram + threshold ----------------
__global__ void hist_kernel() {
    __shared__ int h[NBINS];
    int row = blockIdx.x;
    for (int i = threadIdx.x; i < NBINS; i += blockDim.x) h[i] = 0;
    __syncthreads();
    const float* sc = g_scores + (size_t)row * NKEYS;
    // vectorized 4-wide scan
    const float4* sc4 = (const float4*)sc;
    for (int i = threadIdx.x; i < NKEYS / 4; i += blockDim.x) {
        float4 v = sc4[i];
        atomicAdd(&h[monof(v.x) >> 19], 1);
        atomicAdd(&h[monof(v.y) >> 19], 1);
        atomicAdd(&h[monof(v.z) >> 19], 1);
        atomicAdd(&h[monof(v.w) >> 19], 1);
    }
    __syncthreads();
    if (threadIdx.x == 0) {
        int cum = 0, t = 0;
        for (int b = NBINS - 1; b >= 0; --b) {
            cum += h[b];
            if (cum >= TOPK) { t = b; break; }
        }
        g_thr[row] = t;
    }
}

// ---------------- kernel 4: gather candidates >= threshold bin ----------------
__global__ void gather_kernel() {
    int row = blockIdx.x;
    int thr = g_thr[row];
    const float4* sc4 = (const float4*)(g_scores + (size_t)row * NKEYS);
    for (int i = threadIdx.x; i < NKEYS / 4; i += blockDim.x) {
        float4 v = sc4[i];
        float f[4] = { v.x, v.y, v.z, v.w };
#pragma unroll
        for (int l = 0; l < 4; ++l) {
            unsigned m = monof(f[l]);
            if ((int)(m >> 19) >= thr) {
                int pos = atomicAdd(&g_cand_count[row], 1);
                if (pos < CAND_CAP) {
                    unsigned idx = (unsigned)(i * 4 + l);
                    // key packs (score desc, idx asc): tie -> smaller idx wins
                    g_cand[(size_t)row * CAND_CAP + pos] =
                        ((unsigned long long)m << 32) |
                        (unsigned long long)(0xFFFFFFFFu - idx);
                }
            }
        }
    }
}

// ---------------- kernel 5: bitonic sort candidates, emit sorted top-256 ----------------
__global__ void sort_kernel() {
    __shared__ unsigned long long s[CAND_CAP];
    int row = blockIdx.x;
    int cnt = min(g_cand_count[row], CAND_CAP);
    int P = 256;
    while (P < cnt) P <<= 1;
    for (int i = threadIdx.x; i < P; i += blockDim.x)
        s[i] = (i < cnt) ? g_cand[(size_t)row * CAND_CAP + i] : 0ULL;  // 0 sorts last
    __syncthreads();
    for (int k = 2; k <= P; k <<= 1) {
        for (int j = k >> 1; j > 0; j >>= 1) {
            for (int i = threadIdx.x; i < P; i += blockDim.x) {
                int p = i ^ j;
                if (p > i) {
                    bool up = ((i & k) != 0);     // overall descending
                    unsigned long long a = s[i], b = s[p];
                    if ((a > b) == up) { s[i] = b; s[p] = a; }
                }
            }
            __syncthreads();
        }
    }
    for (int i = threadIdx.x; i < TOPK; i += blockDim.x) {
        unsigned long long key = s[i];
        g_topk_score[row * TOPK + i] = unmonof((unsigned)(key >> 32));
        g_topk_idx[row * TOPK + i]   = (int)(0xFFFFFFFFu - (unsigned)(key & 0xFFFFFFFFu));
    }
}

// ---------------- kernel 6: softmax + y_hat + margin loss ----------------
__global__ void finalize_kernel(const int* __restrict__ yv,
                                const int* __restrict__ values,
                                float* __restrict__ out) {
    __shared__ float rs[TOPK], rp[TOPK], rn[TOPK];
    __shared__ int   rc[TOPK];
    int row = blockIdx.x;
    int j   = threadIdx.x;
    float sco = g_topk_score[row * TOPK + j];
    int   id  = g_topk_idx[row * TOPK + j];
    int   v   = values[id];
    int   yr  = yv[row];
    float c   = (v == yr) ? 1.0f : 0.0f;
    float mx  = g_topk_score[row * TOPK];         // sorted: element 0 is max
    float e   = expf(sco - mx);                   // TEMP = 1
    rs[j] = e;
    rp[j] = sco * c;                              // cos*correct (zeros included) -> max
    rn[j] = sco * (1.0f - c);
    rc[j] = (int)c;
    __syncthreads();
    for (int st = TOPK / 2; st > 0; st >>= 1) {
        if (j < st) {
            rs[j] += rs[j + st];
            rp[j]  = fmaxf(rp[j], rp[j + st]);
            rn[j]  = fmaxf(rn[j], rn[j + st]);
            rc[j] += rc[j + st];
        }
        __syncthreads();
    }
    float inv = 1.0f / rs[0];
    out[BATCH + row * TOPK + j] = e * inv;        // softmax_score block
    if (j == 0) {
        float pos   = (rc[0] > 0) ? rp[0] : 0.0f; // pos * has_pos
        float lossr = fmaxf(rn[0] - pos + 0.1f, 0.0f);
        atomicAdd(&g_loss, lossr * (1.0f / BATCH));
        out[row] = (float)values[g_topk_idx[row * TOPK]];  // y_hat
    }
}

__global__ void loss_kernel(float* __restrict__ out) {
    out[BATCH + BATCH * TOPK] = g_loss;
}

// ---------------- launch ----------------
extern "C" void kernel_launch(void* const* d_in, const int* in_sizes, int n_in,
                              void* d_out, int out_size) {
    const float* x      = (const float*)d_in[0];
    const int*   y      = (const int*)  d_in[1];
    const float* keys   = (const float*)d_in[2];
    const int*   values = (const int*)  d_in[3];
    const float* W      = (const float*)d_in[4];
    const float* bias   = (const float*)d_in[5];
    float* out = (float*)d_out;

    init_kernel<<<1, 512>>>();
    q_kernel<<<BATCH, DIM>>>(x, W, bias);
    dim3 g(NKEYS / BN, BATCH / BM);
    score_gemm<<<g, 256>>>(keys);
    hist_kernel<<<BATCH, 1024>>>();
    gather_kernel<<<BATCH, 1024>>>();
    sort_kernel<<<BATCH, 1024>>>();
    finalize_kernel<<<BATCH, TOPK>>>(y, values, out);
    loss_kernel<<<1, 1>>>(out);
}

// round 4
// speedup vs baseline: 1.1903x; 1.1903x over previous
#include <cuda_runtime.h>
#include <math.h>
#include <stdint.h>

// Problem dims (fixed by the dataset)
#define BATCH 512
#define DIM   256
#define NKEYS 262144
#define TOPK  256
#define CAND_CAP 4096
#define NBINS 8192          // top 13 bits of monotone float key (fallback only)
#define THR   0.165f        // static candidate filter, ~1090 cands/row expected

// ---------------- device scratch (no allocations allowed) ----------------
__device__ float               g_q[BATCH * DIM];
__device__ int                 g_cand_count[BATCH];
__device__ unsigned long long  g_cand[(size_t)BATCH * CAND_CAP];    // packed (score,idx) keys
__device__ float               g_topk_score[BATCH * TOPK];
__device__ int                 g_topk_idx[BATCH * TOPK];
__device__ float               g_loss;

// Monotone float<->uint mapping: larger float => larger uint
__device__ __forceinline__ unsigned monof(float f) {
    unsigned u = __float_as_uint(f);
    return (u & 0x80000000u) ? ~u : (u | 0x80000000u);
}
__device__ __forceinline__ float unmonof(unsigned m) {
    return (m & 0x80000000u) ? __uint_as_float(m ^ 0x80000000u)
                             : __uint_as_float(~m);
}

// Packed f32x2 helpers (sm_100+): each 64-bit reg holds two IEEE fp32 lanes.
__device__ __forceinline__ void ffma2(unsigned long long& d,
                                      unsigned long long a,
                                      unsigned long long b) {
    asm("fma.rn.f32x2 %0, %1, %2, %0;" : "+l"(d) : "l"(a), "l"(b));
}
__device__ __forceinline__ unsigned long long dup2(float x) {
    unsigned long long r;
    asm("mov.b64 %0, {%1, %1};" : "=l"(r) : "f"(x));
    return r;
}

__device__ __forceinline__ void push_cand(int row, unsigned idx, float f) {
    int pos = atomicAdd(&g_cand_count[row], 1);
    if (pos < CAND_CAP) {
        // key packs (score desc, idx asc): tie -> smaller idx wins (matches jax top_k)
        g_cand[(size_t)row * CAND_CAP + pos] =
            ((unsigned long long)monof(f) << 32) |
            (unsigned long long)(0xFFFFFFFFu - idx);
    }
}

// ---------------- kernel 0: per-launch init ----------------
__global__ void init_kernel() {
    int i = threadIdx.x;
    if (i < BATCH) g_cand_count[i] = 0;
    if (i == 0) g_loss = 0.0f;
}

// ---------------- kernel 1: q = normalize(x @ W^T + b) ----------------
__global__ void q_kernel(const float* __restrict__ x,
                         const float* __restrict__ W,
                         const float* __restrict__ bias) {
    __shared__ float xs[DIM];
    __shared__ float red[DIM];
    int row = blockIdx.x;
    int j   = threadIdx.x;
    xs[j] = x[row * DIM + j];
    __syncthreads();
    const float* wr = W + j * DIM;
    float acc = 0.0f;
#pragma unroll 8
    for (int d = 0; d < DIM; ++d) acc = fmaf(xs[d], wr[d], acc);
    acc += bias[j];
    red[j] = acc * acc;
    __syncthreads();
    for (int s = DIM / 2; s > 0; s >>= 1) {
        if (j < s) red[j] += red[j + s];
        __syncthreads();
    }
    // same scale factor for the whole row -> score ordering is exact
    float inv = rsqrtf(red[0]);
    g_q[row * DIM + j] = acc * inv;
}

// ---------------- kernel 2: fused score GEMM + candidate push --------------
// Tile 128(batch) x 128(keys) x 16(K). 256 threads, 8x8 per thread.
// f32x2 packed accumulators, double-buffered smem (1 barrier / k-tile).
// No score materialization: epilogue pushes score > THR into per-row lists.
#define BM 128
#define BN 128
#define BK 16
__global__ void __launch_bounds__(256)
score_gemm(const float* __restrict__ keys) {
    __shared__ float As[2][BK][BM];
    __shared__ float Bs[2][BK][BN];
    int tid = threadIdx.x;
    int tx  = tid & 15;        // key sub-tile
    int ty  = tid >> 4;        // batch sub-tile
    // grid: x = m-block (fast) so the 4 blocks sharing a key strip are adjacent
    int mBase = blockIdx.x * BM;
    int nBase = blockIdx.y * BN;

    unsigned long long acc[8][4];   // [i][j-pair], each holds 2 fp32 columns
#pragma unroll
    for (int i = 0; i < 8; ++i)
#pragma unroll
        for (int j = 0; j < 4; ++j) acc[i][j] = 0ULL;

    // register prefetch buffers (2 x float4 each for A and B)
    float4 pa[2], pb[2];
    int rowA[2], kkA[2];
#pragma unroll
    for (int r = 0; r < 2; ++r) {
        int f4id = tid + r * 256;          // 0..511
        rowA[r]  = f4id >> 2;              // 0..127
        kkA[r]   = (f4id & 3) * 4;         // 0,4,8,12
    }

    // preload k-tile 0 into registers
#pragma unroll
    for (int r = 0; r < 2; ++r) {
        pa[r] = *(const float4*)&g_q[(size_t)(mBase + rowA[r]) * DIM + kkA[r]];
        pb[r] = *(const float4*)&keys[(size_t)(nBase + rowA[r]) * DIM + kkA[r]];
    }

    int buf = 0;
    for (int k0 = 0; k0 < DIM; k0 += BK, buf ^= 1) {
        // store prefetched regs into current buffer
#pragma unroll
        for (int r = 0; r < 2; ++r) {
            int row = rowA[r], kk4 = kkA[r];
            As[buf][kk4 + 0][row] = pa[r].x; As[buf][kk4 + 1][row] = pa[r].y;
            As[buf][kk4 + 2][row] = pa[r].z; As[buf][kk4 + 3][row] = pa[r].w;
            Bs[buf][kk4 + 0][row] = pb[r].x; Bs[buf][kk4 + 1][row] = pb[r].y;
            Bs[buf][kk4 + 2][row] = pb[r].z; Bs[buf][kk4 + 3][row] = pb[r].w;
        }
        __syncthreads();      // one barrier per k-tile (buffer reuse is 2 barriers apart)
        // issue next tile's global loads before the FFMA burst (latency hiding)
        if (k0 + BK < DIM) {
            int kn = k0 + BK;
#pragma unroll
            for (int r = 0; r < 2; ++r) {
                pa[r] = *(const float4*)&g_q[(size_t)(mBase + rowA[r]) * DIM + kn + kkA[r]];
                pb[r] = *(const float4*)&keys[(size_t)(nBase + rowA[r]) * DIM + kn + kkA[r]];
            }
        }
#pragma unroll
        for (int kk = 0; kk < BK; ++kk) {
            // a: 8 scalars (rows, broadcast within warp), b: 4 packed pairs
            float4 a0 = *(const float4*)&As[buf][kk][ty * 8];
            float4 a1 = *(const float4*)&As[buf][kk][ty * 8 + 4];
            ulonglong2 bp0 = *(const ulonglong2*)&Bs[buf][kk][tx * 8];      // cols 0-3
            ulonglong2 bp1 = *(const ulonglong2*)&Bs[buf][kk][tx * 8 + 4];  // cols 4-7
            unsigned long long b[4] = { bp0.x, bp0.y, bp1.x, bp1.y };
            float a[8] = { a0.x, a0.y, a0.z, a0.w, a1.x, a1.y, a1.z, a1.w };
#pragma unroll
            for (int i = 0; i < 8; ++i) {
                unsigned long long ai = dup2(a[i]);
#pragma unroll
                for (int j = 0; j < 4; ++j) ffma2(acc[i][j], ai, b[j]);
            }
        }
    }

    // epilogue: push candidates above static threshold (no score writes)
#pragma unroll
    for (int i = 0; i < 8; ++i) {
        int row = mBase + ty * 8 + i;
#pragma unroll
        for (int j = 0; j < 4; ++j) {
            float flo = __uint_as_float((unsigned)(acc[i][j] & 0xFFFFFFFFull));
            float fhi = __uint_as_float((unsigned)(acc[i][j] >> 32));
            unsigned col = (unsigned)(nBase + tx * 8 + 2 * j);
            if (flo > THR) push_cand(row, col, flo);
            if (fhi > THR) push_cand(row, col + 1, fhi);
        }
    }
}

// ---------------- kernel 3: correctness fallback (normally exits instantly) --
// If a row's candidate count is out of [TOPK, CAND_CAP], recompute that row's
// scores streaming: hist pass -> threshold bin -> regather pass.
__global__ void fallback_kernel(const float* __restrict__ keys) {
    int row = blockIdx.x;
    int cnt = g_cand_count[row];
    if (cnt >= TOPK && cnt <= CAND_CAP) return;   // 512 loads + exit: ~free

    __shared__ float qs[DIM];
    __shared__ int h[NBINS];
    __shared__ int thr_s;
    for (int i = threadIdx.x; i < DIM; i += blockDim.x) qs[i] = g_q[row * DIM + i];
    for (int i = threadIdx.x; i < NBINS; i += blockDim.x) h[i] = 0;
    __syncthreads();

    for (int k = threadIdx.x; k < NKEYS; k += blockDim.x) {
        const float4* kr = (const float4*)&keys[(size_t)k * DIM];
        float s = 0.0f;
#pragma unroll 8
        for (int d = 0; d < DIM / 4; ++d) {
            float4 v = kr[d];
            s = fmaf(v.x, qs[4 * d], s);     s = fmaf(v.y, qs[4 * d + 1], s);
            s = fmaf(v.z, qs[4 * d + 2], s); s = fmaf(v.w, qs[4 * d + 3], s);
        }
        atomicAdd(&h[monof(s) >> 19], 1);
    }
    __syncthreads();
    if (threadIdx.x == 0) {
        int cum = 0, t = 0;
        for (int b = NBINS - 1; b >= 0; --b) {
            cum += h[b];
            if (cum >= TOPK) { t = b; break; }
        }
        thr_s = t;
        g_cand_count[row] = 0;
    }
    __syncthreads();
    int t = thr_s;
    for (int k = threadIdx.x; k < NKEYS; k += blockDim.x) {
        const float4* kr = (const float4*)&keys[(size_t)k * DIM];
        float s = 0.0f;
#pragma unroll 8
        for (int d = 0; d < DIM / 4; ++d) {
            float4 v = kr[d];
            s = fmaf(v.x, qs[4 * d], s);     s = fmaf(v.y, qs[4 * d + 1], s);
            s = fmaf(v.z, qs[4 * d + 2], s); s = fmaf(v.w, qs[4 * d + 3], s);
        }
        unsigned m = monof(s);
        if ((int)(m >> 19) >= t) push_cand(row, (unsigned)k, s);
    }
}

// ---------------- kernel 4: bitonic sort candidates, emit sorted top-256 ----
__global__ void sort_kernel() {
    __shared__ unsigned long long s[CAND_CAP];
    int row = blockIdx.x;
    int cnt = min(g_cand_count[row], CAND_CAP);
    int P = 256;
    while (P < cnt) P <<= 1;
    for (int i = threadIdx.x; i < P; i += blockDim.x)
        s[i] = (i < cnt) ? g_cand[(size_t)row * CAND_CAP + i] : 0ULL;  // 0 sorts last
    __syncthreads();
    for (int k = 2; k <= P; k <<= 1) {
        for (int j = k >> 1; j > 0; j >>= 1) {
            for (int i = threadIdx.x; i < P; i += blockDim.x) {
                int p = i ^ j;
                if (p > i) {
                    bool up = ((i & k) != 0);     // overall descending
                    unsigned long long a = s[i], b = s[p];
                    if ((a > b) == up) { s[i] = b; s[p] = a; }
                }
            }
            __syncthreads();
        }
    }
    for (int i = threadIdx.x; i < TOPK; i += blockDim.x) {
        unsigned long long key = s[i];
        g_topk_score[row * TOPK + i] = unmonof((unsigned)(key >> 32));
        g_topk_idx[row * TOPK + i]   = (int)(0xFFFFFFFFu - (unsigned)(key & 0xFFFFFFFFu));
    }
}

// ---------------- kernel 5: softmax + y_hat + margin loss ----------------
__global__ void finalize_kernel(const int* __restrict__ yv,
                                const int* __restrict__ values,
                                float* __restrict__ out) {
    __shared__ float rs[TOPK], rp[TOPK], rn[TOPK];
    __shared__ int   rc[TOPK];
    int row = blockIdx.x;
    int j   = threadIdx.x;
    float sco = g_topk_score[row * TOPK + j];
    int   id  = g_topk_idx[row * TOPK + j];
    int   v   = values[id];
    int   yr  = yv[row];
    float c   = (v == yr) ? 1.0f : 0.0f;
    float mx  = g_topk_score[row * TOPK];         // sorted: element 0 is max
    float e   = expf(sco - mx);                   // TEMP = 1
    rs[j] = e;
    rp[j] = sco * c;                              // cos*correct (zeros included) -> max
    rn[j] = sco * (1.0f - c);
    rc[j] = (int)c;
    __syncthreads();
    for (int st = TOPK / 2; st > 0; st >>= 1) {
        if (j < st) {
            rs[j] += rs[j + st];
            rp[j]  = fmaxf(rp[j], rp[j + st]);
            rn[j]  = fmaxf(rn[j], rn[j + st]);
            rc[j] += rc[j + st];
        }
        __syncthreads();
    }
    float inv = 1.0f / rs[0];
    out[BATCH + row * TOPK + j] = e * inv;        // softmax_score block
    if (j == 0) {
        float pos   = (rc[0] > 0) ? rp[0] : 0.0f; // pos * has_pos
        float lossr = fmaxf(rn[0] - pos + 0.1f, 0.0f);
        atomicAdd(&g_loss, lossr * (1.0f / BATCH));
        out[row] = (float)values[g_topk_idx[row * TOPK]];  // y_hat
    }
}

__global__ void loss_kernel(float* __restrict__ out) {
    out[BATCH + BATCH * TOPK] = g_loss;
}

// ---------------- launch ----------------
extern "C" void kernel_launch(void* const* d_in, const int* in_sizes, int n_in,
                              void* d_out, int out_size) {
    const float* x      = (const float*)d_in[0];
    const int*   y      = (const int*)  d_in[1];
    const float* keys   = (const float*)d_in[2];
    const int*   values = (const int*)  d_in[3];
    const float* W      = (const float*)d_in[4];
    const float* bias   = (const float*)d_in[5];
    float* out = (float*)d_out;

    init_kernel<<<1, 512>>>();
    q_kernel<<<BATCH, DIM>>>(x, W, bias);
    dim3 g(BATCH / BM, NKEYS / BN);   // m-block fastest: key-strip sharing in-wave
    score_gemm<<<g, 256>>>(keys);
    fallback_kernel<<<BATCH, 1024>>>(keys);
    sort_kernel<<<BATCH, 1024>>>();
    finalize_kernel<<<BATCH, TOPK>>>(y, values, out);
    loss_kernel<<<1, 1>>>(out);
}